// round 4
// baseline (speedup 1.0000x reference)
#include <cuda_runtime.h>
#include <math_constants.h>

#define N_BOX 1024
#define P_PTS 4096
#define NTHREADS 256
#define NWARPS (NTHREADS / 32)
#define SPLIT 2
#define NBLOCKS (N_BOX * SPLIT)
#define PTS_PER_BLK (P_PTS / SPLIT)          /* 2048 */
#define VEC_PER_BLK (PTS_PER_BLK / 2)        /* 1024 float4 */
#define ITERS (VEC_PER_BLK / NTHREADS)       /* 4 */

#define PI_F      3.14159274101257324219f
#define HALF_PI_F 1.57079637050628662109f

__device__ float g_psum[NBLOCKS];
__device__ int   g_pcnt[NBLOCKS];
__device__ int   g_count;   // zero-init at load; reset by last block each launch

__device__ __forceinline__ float frcp_approx(float x) {
    float r;
    asm("rcp.approx.f32 %0, %1;" : "=f"(r) : "f"(x));
    return r;
}

// slot layout: pair02 = slots {0,1} (preferred first), pair13 = slots {2,3}
struct BoxConsts {
    float k1, k2;
    float bsA, bsB;   // pair02: |bsA| <= |bsB| (tie keeps original edge order 0,2)
    float bsC, bsD;   // pair13
    float MX[4], WX[4];   // u-space x-interval midpoint/halfwidth per slot
    float MY[4], WY[4];   // v-space y-interval
};

// convert ix-space open interval (lo, hi) on ix = bs*u into u-space |u-MID|<HW
__device__ __forceinline__ void make_interval(float lo, float hi, float bs,
                                              float& MID, float& HW)
{
    if (lo >= hi) {                 // empty interval (degenerate edge)
        MID = 0.0f; HW = -1.0f;
    } else if (bs == 0.0f) {        // ix == 0 always: inside iff 0 in (lo,hi)
        MID = 0.0f;
        HW = (lo < 0.0f && 0.0f < hi) ? CUDART_INF_F : -1.0f;
    } else {
        const float a = __fdividef(lo, bs);
        const float b = __fdividef(hi, bs);
        const float A = fminf(a, b), B = fmaxf(a, b);
        MID = 0.5f * (A + B);
        HW  = 0.5f * (B - A);
    }
}

__global__ __launch_bounds__(NTHREADS)
void wdm3d_fused_kernel(const float*  __restrict__ wl,
                        const float*  __restrict__ Ry,
                        const float4* __restrict__ points4,
                        const float2* __restrict__ density2,
                        const float*  __restrict__ center,
                        float* __restrict__ out)
{
    const int blk  = blockIdx.x;
    const int n    = blk >> 1;
    const int half = blk & 1;
    __shared__ BoxConsts C;

    const unsigned full = 0xFFFFFFFFu;

    // ---------------- per-box constants: warp 0 (sincos parallel over 4 lanes)
    if (threadIdx.x < 32) {
        const int lane = threadIdx.x;
        const float w  = wl[2 * n];
        const float l  = wl[2 * n + 1];
        const float ry = Ry[n];
        const float ccx = center[2 * n];
        const float ccy = center[2 * n + 1];

        const float init_theta = atanf(w / l);
        const float len = sqrtf(w * w + l * l) * 0.5f;

        const int j = lane & 3;
        float ang = init_theta + ry;                         // j==0
        if (j == 1) ang = (PI_F - init_theta) + ry;
        if (j == 2) ang = (PI_F + init_theta) + ry;
        if (j == 3) ang = (-init_theta) + ry;
        float sj, cj;
        sincosf(ang, &sj, &cj);
        const float cxl = len * cj + ccx;
        const float cyl = len * sj + ccy;

        const float cx0 = __shfl_sync(full, cxl, 0), cy0 = __shfl_sync(full, cyl, 0);
        const float cx1 = __shfl_sync(full, cxl, 1), cy1 = __shfl_sync(full, cyl, 1);
        const float cx2 = __shfl_sync(full, cxl, 2), cy2 = __shfl_sync(full, cyl, 2);
        const float cx3 = __shfl_sync(full, cxl, 3), cy3 = __shfl_sync(full, cyl, 3);

        float ry2 = (ry == HALF_PI_F) ? (ry - 0.0001f) : ry;
        ry2 = (ry2 == 0.0f) ? (ry2 + 0.0001f) : ry2;
        const float k1 = tanf(ry2);
        const float k2 = tanf(ry2 + HALF_PI_F);

        // edge j: slope ks[j], intercept bs[j], bounds from corners j,(j+1)%4
        float bs[4];
        bs[0] = cy0 - k1 * cx0;   // b11
        bs[1] = cy2 - k2 * cx2;   // b22
        bs[2] = cy2 - k1 * cx2;   // b12
        bs[3] = cy0 - k2 * cx0;   // b21

        const float cxr[4] = { rintf(cx0 * 1e4f), rintf(cx1 * 1e4f),
                               rintf(cx2 * 1e4f), rintf(cx3 * 1e4f) };
        const float cyr[4] = { rintf(cy0 * 1e4f), rintf(cy1 * 1e4f),
                               rintf(cy2 * 1e4f), rintf(cy3 * 1e4f) };

        // per-edge u/v-space intervals
        float MX[4], WX[4], MY[4], WY[4];
        const float S = 1e-4f;
#pragma unroll
        for (int e = 0; e < 4; e++) {
            const int e2 = (e + 1) & 3;
            const float lox = (fminf(cxr[e], cxr[e2]) + 0.5f) * S;
            const float hix = (fmaxf(cxr[e], cxr[e2]) - 0.5f) * S;
            const float loy = (fminf(cyr[e], cyr[e2]) + 0.5f) * S;
            const float hiy = (fmaxf(cyr[e], cyr[e2]) - 0.5f) * S;
            make_interval(lox, hix, bs[e], MX[e], WX[e]);
            make_interval(loy, hiy, bs[e], MY[e], WY[e]);
        }

        // pair (0,2): preferred slot = smaller |bs| (tie: edge 0 first)
        int p0 = 0, p2 = 2;
        if (fabsf(bs[2]) < fabsf(bs[0])) { p0 = 2; p2 = 0; }
        int p1 = 1, p3 = 3;
        if (fabsf(bs[3]) < fabsf(bs[1])) { p1 = 3; p3 = 1; }

        if (lane == 0) {
            C.k1 = k1; C.k2 = k2;
            C.bsA = bs[p0]; C.bsB = bs[p2];
            C.bsC = bs[p1]; C.bsD = bs[p3];
            C.MX[0] = MX[p0]; C.WX[0] = WX[p0]; C.MY[0] = MY[p0]; C.WY[0] = WY[p0];
            C.MX[1] = MX[p2]; C.WX[1] = WX[p2]; C.MY[1] = MY[p2]; C.WY[1] = WY[p2];
            C.MX[2] = MX[p1]; C.WX[2] = WX[p1]; C.MY[2] = MY[p1]; C.WY[2] = WY[p1];
            C.MX[3] = MX[p3]; C.WX[3] = WX[p3]; C.MY[3] = MY[p3]; C.WY[3] = WY[p3];
        }
    }
    __syncthreads();

    const float k1 = C.k1, k2 = C.k2;
    const float bsA = C.bsA, bsB = C.bsB, bsC = C.bsC, bsD = C.bsD;
    const float MX0 = C.MX[0], WX0 = C.WX[0], MY0 = C.MY[0], WY0 = C.WY[0];
    const float MX1 = C.MX[1], WX1 = C.WX[1], MY1 = C.MY[1], WY1 = C.WY[1];
    const float MX2 = C.MX[2], WX2 = C.WX[2], MY2 = C.MY[2], WY2 = C.WY[2];
    const float MX3 = C.MX[3], WX3 = C.WX[3], MY3 = C.MY[3], WY3 = C.WY[3];

    const size_t base = (size_t)n * (P_PTS / 2) + (size_t)half * VEC_PER_BLK;
    const float4* __restrict__ pts = points4  + base;
    const float2* __restrict__ den = density2 + base;

    float sum = 0.0f;
    int   cnt = 0;

#define PROCESS_POINT(PX_, PY_, DENS_)                                          \
    do {                                                                        \
        const float px = ((PX_) == 0.0f) ? 0.0001f : (PX_);                     \
        const float py = (PY_);                                                 \
        const float r1 = frcp_approx(fmaf(-k1, px, py));                        \
        const float r2 = frcp_approx(fmaf(-k2, px, py));                        \
        const float u1 = px * r1, v1 = py * r1;                                 \
        const float u2 = px * r2, v2 = py * r2;                                 \
        /* slot masks: |u-MID| < HW (open intervals, pre-scaled)             */ \
        const bool mA = (fabsf(u1 - MX0) < WX0) || (fabsf(v1 - MY0) < WY0);     \
        const bool mB = (fabsf(u1 - MX1) < WX1) || (fabsf(v1 - MY1) < WY1);     \
        const bool mC = (fabsf(u2 - MX2) < WX2) || (fabsf(v2 - MY2) < WY2);     \
        const bool mD = (fabsf(u2 - MX3) < WX3) || (fabsf(v2 - MY3) < WY3);     \
        const int pc = (int)mA + (int)mB + (int)mC + (int)mD;                   \
        /* within-pair winner pre-decided by |bs| ordering                   */ \
        const float bs02 = mA ? bsA : bsB;                                      \
        const float bs13 = mC ? bsC : bsD;                                      \
        const float c02 = (mA || mB) ? fabsf(bs02 * u1) : CUDART_INF_F;         \
        const float c13 = (mC || mD) ? fabsf(bs13 * u2) : CUDART_INF_F;         \
        const bool firstPair = (c02 <= c13);                                    \
        const float bw = firstPair ? bs02 : bs13;                               \
        const float uw = firstPair ? u1 : u2;                                   \
        const float vw = firstPair ? v1 : v2;                                   \
        if (pc == 2) {                                                          \
            const float ix = bw * uw, iy = bw * vw;                             \
            const float dsel = fabsf(ix - px) + fabsf(iy - py);                 \
            sum += dsel * frcp_approx(DENS_);                                   \
            cnt += 1;                                                           \
        }                                                                       \
    } while (0)

    // front-batched loads for MLP, then compute
    float4 p[ITERS];
    float2 d[ITERS];
#pragma unroll
    for (int it = 0; it < ITERS; it++) {
        p[it] = pts[threadIdx.x + it * NTHREADS];
        d[it] = den[threadIdx.x + it * NTHREADS];
    }
#pragma unroll
    for (int it = 0; it < ITERS; it++) {
        PROCESS_POINT(p[it].x, p[it].y, d[it].x);
        PROCESS_POINT(p[it].z, p[it].w, d[it].y);
    }

    // ---------------- block reduction
#pragma unroll
    for (int off = 16; off > 0; off >>= 1) {
        sum += __shfl_down_sync(full, sum, off);
        cnt += __shfl_down_sync(full, cnt, off);
    }

    __shared__ float s_sum[NWARPS];
    __shared__ int   s_cnt[NWARPS];
    __shared__ bool  s_last;
    const int warp = threadIdx.x >> 5;
    const int lane = threadIdx.x & 31;
    if (lane == 0) { s_sum[warp] = sum; s_cnt[warp] = cnt; }
    __syncthreads();

    if (threadIdx.x == 0) {
        float fs = 0.0f; int fc = 0;
#pragma unroll
        for (int wi = 0; wi < NWARPS; wi++) { fs += s_sum[wi]; fc += s_cnt[wi]; }
        g_psum[blk] = fs;
        g_pcnt[blk] = fc;
        __threadfence();
        const int prev = atomicAdd(&g_count, 1);
        s_last = (prev == gridDim.x - 1);
    }
    __syncthreads();

    // ---------------- last block: deterministic final reduction over boxes
    if (s_last) {
        float fs = 0.0f;
        int   fv = 0;
#pragma unroll
        for (int jb = 0; jb < N_BOX / NTHREADS; jb++) {
            const int b = threadIdx.x + jb * NTHREADS;
            const float bsum = __ldcg(&g_psum[2 * b]) + __ldcg(&g_psum[2 * b + 1]);
            const int   bcnt = __ldcg(&g_pcnt[2 * b]) + __ldcg(&g_pcnt[2 * b + 1]);
            const bool valid = (bcnt >= 3);
            fs += valid ? (bsum / (float)max(bcnt, 1)) : 0.0f;
            fv += valid ? 1 : 0;
        }
#pragma unroll
        for (int off = 16; off > 0; off >>= 1) {
            fs += __shfl_down_sync(full, fs, off);
            fv += __shfl_down_sync(full, fv, off);
        }
        __shared__ float f_sum[NWARPS];
        __shared__ int   f_cnt[NWARPS];
        if (lane == 0) { f_sum[warp] = fs; f_cnt[warp] = fv; }
        __syncthreads();
        if (threadIdx.x == 0) {
            float ts = 0.0f; int tv = 0;
#pragma unroll
            for (int wi = 0; wi < NWARPS; wi++) { ts += f_sum[wi]; tv += f_cnt[wi]; }
            out[0] = ts / (float)max(tv, 1);
            g_count = 0;
        }
    }
}

extern "C" void kernel_launch(void* const* d_in, const int* in_sizes, int n_in,
                              void* d_out, int out_size)
{
    const float*  wl       = (const float*)d_in[0];
    const float*  Ry       = (const float*)d_in[1];
    const float4* points4  = (const float4*)d_in[2];
    const float2* density2 = (const float2*)d_in[3];
    const float*  center   = (const float*)d_in[4];
    float* out = (float*)d_out;

    wdm3d_fused_kernel<<<NBLOCKS, NTHREADS>>>(wl, Ry, points4, density2, center, out);
}